// round 11
// baseline (speedup 1.0000x reference)
#include <cuda_runtime.h>
#include <math.h>
#include <float.h>

// VIN forward: B=128, L_I=2, L_H=150, L_Q=10, IMSIZE=64, K=40, NOUT=8
// r = conv3x3(x, cw) + cb  with cw[i] = sum_h r_w[h]*h_w[h,i], cb = sum_h r_w[h]*h_b[h]
// eval_q(v) = conv3x3(r, q_w) + conv3x3(v, w).  If w == 0 the K-step scan is a
// fixed point and q == conv3x3(r, q_w): only a 5x5 input patch per batch matters.
//
// FINAL converged configuration. Identical-binary measurements: 6.176, 6.176,
// 6.592, 6.976us -> noise band +-0.4us; all structural perturbations tried
// (shfl tail, 256-thread CTA, A-fold tail) were neutral-or-worse. Remaining
// time is graph-replay/launch overhead + depressed clock, outside kernel control.
// (R10 bench was an infra container failure, not a kernel result.)
//   20 warps/CTA, 1 CTA/batch, single wave of 128 CTAs.
//   warps 0-18 : one combined weight each (warp-shuffle reduction over 150 terms)
//   warp 19    : loader -- state_x/y first (longest dependent chain), then the
//                5x5x2 input patch and small weights (w, q_w, fc_w) into smem
//   tail       : warp 0, smem-staged stages
// Slow-path v field lives in gmem scratch so static smem stays ~1.5KB.

#define BATCH 128
#define L_I 2
#define L_H 150
#define L_Q 10
#define IMS 64
#define NOUT 8
#define NTHREADS 640
#define VSTR 68            // slow-path v row stride (66 rows x 68 cols, 1-halo)
#define VSZ (66 * VSTR)

// general-path scratch (never touched on the fast path)
__device__ float g_r[BATCH * IMS * IMS];
__device__ float g_qr[BATCH * L_Q * IMS * IMS];
__device__ float g_v[BATCH * 2 * VSZ];

__global__ __launch_bounds__(NTHREADS, 1) void vin_kernel(
    const float* __restrict__ input_view,   // [B, L_I, 64, 64]
    const int*   __restrict__ state_x,      // [B]
    const int*   __restrict__ state_y,      // [B]
    const int*   __restrict__ kptr,         // scalar K (may be null)
    const float* __restrict__ h_w,          // [L_H, L_I, 3, 3]
    const float* __restrict__ h_b,          // [L_H]
    const float* __restrict__ r_w,          // [L_H]
    const float* __restrict__ q_w,          // [L_Q, 1, 3, 3]
    const float* __restrict__ w,            // [L_Q, 1, 3, 3]
    const float* __restrict__ fc_w,         // [NOUT, L_Q]
    float* __restrict__ out, int half_off)
{
    const int b    = blockIdx.x;
    const int tid  = threadIdx.x;
    const int wid  = tid >> 5;
    const int lane = tid & 31;

    __shared__ float comb[19];              // cw[0..17], cb at [18]
    __shared__ float patch[L_I][6][6];      // 5x5 used, zero-filled OOB
    __shared__ float qw_s[L_Q * 9];
    __shared__ float w_s[L_Q * 9];
    __shared__ float fc_s[NOUT * L_Q];
    __shared__ int   wz, sx_s, sy_s;
    __shared__ float r9[9];
    __shared__ float qv[L_Q];

    // ---------------- warps 0-18: combined-weight reduction -----------------
    if (wid < 19) {
        float s = 0.f;
        if (wid < 18) {
            #pragma unroll
            for (int j = 0; j < 5; ++j) {
                const int h = lane + j * 32;
                if (h < L_H) s += r_w[h] * h_w[h * (L_I * 9) + wid];
            }
        } else {
            #pragma unroll
            for (int j = 0; j < 5; ++j) {
                const int h = lane + j * 32;
                if (h < L_H) s += r_w[h] * h_b[h];
            }
        }
        #pragma unroll
        for (int off = 16; off > 0; off >>= 1)
            s += __shfl_down_sync(0xffffffffu, s, off);
        if (lane == 0) comb[wid] = s;
    }
    // ---------------- warp 19: loader (state first — longest chain) ----------
    else {
        const int sx = state_x[b];           // issue the dependent chain ASAP
        const int sy = state_y[b];
        if (lane == 0) { sx_s = sx; sy_s = sy; }
        const float* inb = input_view + (size_t)b * L_I * IMS * IMS;
        #pragma unroll
        for (int e = lane; e < L_I * 25; e += 32) {
            const int i  = e / 25;
            const int rm = e % 25;
            const int dy = rm / 5, dx = rm % 5;
            const int y = sx + dy - 2, x = sy + dx - 2;
            float v = 0.f;
            if ((unsigned)y < IMS && (unsigned)x < IMS)
                v = inb[(i * IMS + y) * IMS + x];
            patch[i][dy][dx] = v;
        }
        // small weights (independent of state chain)
        #pragma unroll
        for (int e = lane; e < L_Q * 9; e += 32) qw_s[e] = q_w[e];
        bool nz = false;
        #pragma unroll
        for (int e = lane; e < L_Q * 9; e += 32) {
            const float val = w[e];
            w_s[e] = val;
            nz |= (val != 0.f);
        }
        #pragma unroll
        for (int e = lane; e < NOUT * L_Q; e += 32) fc_s[e] = fc_w[e];
        const unsigned bal = __ballot_sync(0xffffffffu, nz);
        if (lane == 0) wz = (bal != 0u);
    }
    __syncthreads();

    // =========================== FAST PATH (w == 0) ===========================
    if (wz == 0) {
        if (wid == 0) {
            if (lane < 9) {
                const int ry = lane / 3, rx = lane % 3;       // 0..2
                const int y = sx_s + ry - 1, x = sy_s + rx - 1;
                float rv = 0.f;
                if ((unsigned)y < IMS && (unsigned)x < IMS) {
                    rv = comb[18];
                    #pragma unroll
                    for (int i = 0; i < L_I; ++i)
                        #pragma unroll
                        for (int kh = 0; kh < 3; ++kh)
                            #pragma unroll
                            for (int kw = 0; kw < 3; ++kw)
                                rv += comb[i * 9 + kh * 3 + kw] * patch[i][ry + kh][rx + kw];
                }
                r9[lane] = rv;
            }
            __syncwarp();
            if (lane < L_Q) {
                float s = 0.f;
                #pragma unroll
                for (int t = 0; t < 9; ++t) s += qw_s[lane * 9 + t] * r9[t];
                qv[lane] = s;
            }
            __syncwarp();
            // all 32 lanes compute a (duplicated) logit so full-mask shfl is legal
            const int o = lane & 7;
            float lg = 0.f;
            #pragma unroll
            for (int q = 0; q < L_Q; ++q) lg += fc_s[o * L_Q + q] * qv[q];
            float mx = lg;
            #pragma unroll
            for (int off = 4; off > 0; off >>= 1)
                mx = fmaxf(mx, __shfl_xor_sync(0xffffffffu, mx, off));
            const float ex = __expf(lg - mx);
            float den = ex;
            #pragma unroll
            for (int off = 4; off > 0; off >>= 1)
                den += __shfl_xor_sync(0xffffffffu, den, off);
            // lanes 0-7 store logits, lanes 8-15 store probs (same o = lane & 7)
            if (lane < 16) {
                if (lane < 8) out[b * NOUT + o] = lg;
                else          out[half_off + b * NOUT + o] = __fdividef(ex, den);
            }
        }
        return;
    }

    // ======================= GENERAL PATH (w != 0) ============================
    const int sx = sx_s, sy = sy_s;
    const float* inb = input_view + (size_t)b * L_I * IMS * IMS;
    float* v_g = g_v + (size_t)b * 2 * VSZ;

    for (int p = tid; p < 2 * VSZ; p += NTHREADS) v_g[p] = 0.f;

    // r field -> gmem scratch
    float* rb = g_r + (size_t)b * IMS * IMS;
    for (int p = tid; p < IMS * IMS; p += NTHREADS) {
        const int y = p >> 6, x = p & 63;
        float s = comb[18];
        #pragma unroll
        for (int i = 0; i < L_I; ++i)
            #pragma unroll
            for (int kh = 0; kh < 3; ++kh) {
                const int yy = y + kh - 1;
                if ((unsigned)yy >= IMS) continue;
                #pragma unroll
                for (int kw = 0; kw < 3; ++kw) {
                    const int xx = x + kw - 1;
                    if ((unsigned)xx >= IMS) continue;
                    s += comb[i * 9 + kh * 3 + kw] * inb[(i * IMS + yy) * IMS + xx];
                }
            }
        rb[p] = s;
    }
    __syncthreads();

    // qr field -> gmem scratch; v0 = max_q qr
    float* qrb = g_qr + (size_t)b * L_Q * IMS * IMS;
    int cur = 0;
    for (int p = tid; p < IMS * IMS; p += NTHREADS) {
        const int y = p >> 6, x = p & 63;
        float m = -FLT_MAX;
        #pragma unroll
        for (int q = 0; q < L_Q; ++q) {
            float s = 0.f;
            #pragma unroll
            for (int kh = 0; kh < 3; ++kh) {
                const int yy = y + kh - 1;
                if ((unsigned)yy >= IMS) continue;
                #pragma unroll
                for (int kw = 0; kw < 3; ++kw) {
                    const int xx = x + kw - 1;
                    if ((unsigned)xx >= IMS) continue;
                    s += qw_s[q * 9 + kh * 3 + kw] * rb[yy * IMS + xx];
                }
            }
            qrb[q * (IMS * IMS) + p] = s;
            m = fmaxf(m, s);
        }
        v_g[cur * VSZ + (y + 1) * VSTR + (x + 1)] = m;
    }
    __syncthreads();

    const int K = kptr ? kptr[0] : 40;
    for (int it = 0; it < K; ++it) {
        const int nxt = cur ^ 1;
        for (int p = tid; p < IMS * IMS; p += NTHREADS) {
            const int y = p >> 6, x = p & 63;
            const float* vb = v_g + cur * VSZ + y * VSTR + x;
            const float v00 = vb[0],        v01 = vb[1],            v02 = vb[2];
            const float v10 = vb[VSTR],     v11 = vb[VSTR + 1],     v12 = vb[VSTR + 2];
            const float v20 = vb[2 * VSTR], v21 = vb[2 * VSTR + 1], v22 = vb[2 * VSTR + 2];
            float m = -FLT_MAX;
            #pragma unroll
            for (int q = 0; q < L_Q; ++q) {
                const float* wq = w_s + q * 9;
                float s = qrb[q * (IMS * IMS) + p]
                        + wq[0] * v00 + wq[1] * v01 + wq[2] * v02
                        + wq[3] * v10 + wq[4] * v11 + wq[5] * v12
                        + wq[6] * v20 + wq[7] * v21 + wq[8] * v22;
                m = fmaxf(m, s);
            }
            v_g[nxt * VSZ + (y + 1) * VSTR + (x + 1)] = m;
        }
        cur = nxt;
        __syncthreads();
    }

    if (tid < L_Q) {
        const float* vb = v_g + cur * VSZ + sx * VSTR + sy;
        const float* wq = w_s + tid * 9;
        qv[tid] = qrb[tid * (IMS * IMS) + sx * IMS + sy]
                + wq[0] * vb[0]        + wq[1] * vb[1]            + wq[2] * vb[2]
                + wq[3] * vb[VSTR]     + wq[4] * vb[VSTR + 1]     + wq[5] * vb[VSTR + 2]
                + wq[6] * vb[2 * VSTR] + wq[7] * vb[2 * VSTR + 1] + wq[8] * vb[2 * VSTR + 2];
    }
    __syncthreads();
    if (tid == 0) {
        float lg[NOUT], mx = -FLT_MAX;
        #pragma unroll
        for (int o = 0; o < NOUT; ++o) {
            float s = 0.f;
            #pragma unroll
            for (int q = 0; q < L_Q; ++q) s += fc_s[o * L_Q + q] * qv[q];
            lg[o] = s;
            mx = fmaxf(mx, s);
        }
        float den = 0.f, ex[NOUT];
        #pragma unroll
        for (int o = 0; o < NOUT; ++o) { ex[o] = __expf(lg[o] - mx); den += ex[o]; }
        const float inv = 1.f / den;
        #pragma unroll
        for (int o = 0; o < NOUT; ++o) {
            out[b * NOUT + o] = lg[o];
            out[half_off + b * NOUT + o] = ex[o] * inv;
        }
    }
}

extern "C" void kernel_launch(void* const* d_in, const int* in_sizes, int n_in,
                              void* d_out, int out_size) {
    const float* input_view = (const float*)d_in[0];
    const int*   state_x    = (const int*)d_in[1];
    const int*   state_y    = (const int*)d_in[2];

    int base = 3;
    const int* kptr = nullptr;
    if (n_in >= 10) { kptr = (const int*)d_in[3]; base = 4; }

    const float* h_w  = (const float*)d_in[base + 0];
    const float* h_b  = (const float*)d_in[base + 1];
    const float* r_w  = (const float*)d_in[base + 2];
    const float* q_w  = (const float*)d_in[base + 3];
    const float* w    = (const float*)d_in[base + 4];
    const float* fc_w = (const float*)d_in[base + 5];

    const int half_off = out_size / 2;   // logits first half, softmax second half

    vin_kernel<<<BATCH, NTHREADS>>>(input_view, state_x, state_y, kptr,
                                    h_w, h_b, r_w, q_w, w, fc_w,
                                    (float*)d_out, half_off);
}

// round 13
// speedup vs baseline: 1.1295x; 1.1295x over previous
#include <cuda_runtime.h>
#include <math.h>
#include <float.h>

// VIN forward: B=128, L_I=2, L_H=150, L_Q=10, IMSIZE=64, K=40, NOUT=8
// r = conv3x3(x, cw) + cb  with cw[i] = sum_h r_w[h]*h_w[h,i], cb = sum_h r_w[h]*h_b[h]
// eval_q(v) = conv3x3(r, q_w) + conv3x3(v, w).  If w == 0 the K-step scan is a
// fixed point and q == conv3x3(r, q_w): only a 5x5 input patch per batch matters.
//
// FINAL converged configuration. Identical-binary measurements: 6.176, 6.176,
// 6.592, 6.976, 6.976us -> noise band +-0.4us. All structural perturbations
// tried (shfl tail, 256-thread CTA, A-fold tail) were neutral-or-worse.
// Remaining time is graph-replay/launch overhead + depressed clock on a
// sub-10us kernel, outside kernel control. (R10/R12 benches were infra
// container failures, not kernel results.)
//   20 warps/CTA, 1 CTA/batch, single wave of 128 CTAs.
//   warps 0-18 : one combined weight each (warp-shuffle reduction over 150 terms)
//   warp 19    : loader -- state_x/y first (longest dependent chain), then the
//                5x5x2 input patch and small weights (w, q_w, fc_w) into smem
//   tail       : warp 0, smem-staged stages
// Slow-path v field lives in gmem scratch so static smem stays ~1.5KB.

#define BATCH 128
#define L_I 2
#define L_H 150
#define L_Q 10
#define IMS 64
#define NOUT 8
#define NTHREADS 640
#define VSTR 68            // slow-path v row stride (66 rows x 68 cols, 1-halo)
#define VSZ (66 * VSTR)

// general-path scratch (never touched on the fast path)
__device__ float g_r[BATCH * IMS * IMS];
__device__ float g_qr[BATCH * L_Q * IMS * IMS];
__device__ float g_v[BATCH * 2 * VSZ];

__global__ __launch_bounds__(NTHREADS, 1) void vin_kernel(
    const float* __restrict__ input_view,   // [B, L_I, 64, 64]
    const int*   __restrict__ state_x,      // [B]
    const int*   __restrict__ state_y,      // [B]
    const int*   __restrict__ kptr,         // scalar K (may be null)
    const float* __restrict__ h_w,          // [L_H, L_I, 3, 3]
    const float* __restrict__ h_b,          // [L_H]
    const float* __restrict__ r_w,          // [L_H]
    const float* __restrict__ q_w,          // [L_Q, 1, 3, 3]
    const float* __restrict__ w,            // [L_Q, 1, 3, 3]
    const float* __restrict__ fc_w,         // [NOUT, L_Q]
    float* __restrict__ out, int half_off)
{
    const int b    = blockIdx.x;
    const int tid  = threadIdx.x;
    const int wid  = tid >> 5;
    const int lane = tid & 31;

    __shared__ float comb[19];              // cw[0..17], cb at [18]
    __shared__ float patch[L_I][6][6];      // 5x5 used, zero-filled OOB
    __shared__ float qw_s[L_Q * 9];
    __shared__ float w_s[L_Q * 9];
    __shared__ float fc_s[NOUT * L_Q];
    __shared__ int   wz, sx_s, sy_s;
    __shared__ float r9[9];
    __shared__ float qv[L_Q];

    // ---------------- warps 0-18: combined-weight reduction -----------------
    if (wid < 19) {
        float s = 0.f;
        if (wid < 18) {
            #pragma unroll
            for (int j = 0; j < 5; ++j) {
                const int h = lane + j * 32;
                if (h < L_H) s += r_w[h] * h_w[h * (L_I * 9) + wid];
            }
        } else {
            #pragma unroll
            for (int j = 0; j < 5; ++j) {
                const int h = lane + j * 32;
                if (h < L_H) s += r_w[h] * h_b[h];
            }
        }
        #pragma unroll
        for (int off = 16; off > 0; off >>= 1)
            s += __shfl_down_sync(0xffffffffu, s, off);
        if (lane == 0) comb[wid] = s;
    }
    // ---------------- warp 19: loader (state first — longest chain) ----------
    else {
        const int sx = state_x[b];           // issue the dependent chain ASAP
        const int sy = state_y[b];
        if (lane == 0) { sx_s = sx; sy_s = sy; }
        const float* inb = input_view + (size_t)b * L_I * IMS * IMS;
        #pragma unroll
        for (int e = lane; e < L_I * 25; e += 32) {
            const int i  = e / 25;
            const int rm = e % 25;
            const int dy = rm / 5, dx = rm % 5;
            const int y = sx + dy - 2, x = sy + dx - 2;
            float v = 0.f;
            if ((unsigned)y < IMS && (unsigned)x < IMS)
                v = inb[(i * IMS + y) * IMS + x];
            patch[i][dy][dx] = v;
        }
        // small weights (independent of state chain)
        #pragma unroll
        for (int e = lane; e < L_Q * 9; e += 32) qw_s[e] = q_w[e];
        bool nz = false;
        #pragma unroll
        for (int e = lane; e < L_Q * 9; e += 32) {
            const float val = w[e];
            w_s[e] = val;
            nz |= (val != 0.f);
        }
        #pragma unroll
        for (int e = lane; e < NOUT * L_Q; e += 32) fc_s[e] = fc_w[e];
        const unsigned bal = __ballot_sync(0xffffffffu, nz);
        if (lane == 0) wz = (bal != 0u);
    }
    __syncthreads();

    // =========================== FAST PATH (w == 0) ===========================
    if (wz == 0) {
        if (wid == 0) {
            if (lane < 9) {
                const int ry = lane / 3, rx = lane % 3;       // 0..2
                const int y = sx_s + ry - 1, x = sy_s + rx - 1;
                float rv = 0.f;
                if ((unsigned)y < IMS && (unsigned)x < IMS) {
                    rv = comb[18];
                    #pragma unroll
                    for (int i = 0; i < L_I; ++i)
                        #pragma unroll
                        for (int kh = 0; kh < 3; ++kh)
                            #pragma unroll
                            for (int kw = 0; kw < 3; ++kw)
                                rv += comb[i * 9 + kh * 3 + kw] * patch[i][ry + kh][rx + kw];
                }
                r9[lane] = rv;
            }
            __syncwarp();
            if (lane < L_Q) {
                float s = 0.f;
                #pragma unroll
                for (int t = 0; t < 9; ++t) s += qw_s[lane * 9 + t] * r9[t];
                qv[lane] = s;
            }
            __syncwarp();
            // all 32 lanes compute a (duplicated) logit so full-mask shfl is legal
            const int o = lane & 7;
            float lg = 0.f;
            #pragma unroll
            for (int q = 0; q < L_Q; ++q) lg += fc_s[o * L_Q + q] * qv[q];
            float mx = lg;
            #pragma unroll
            for (int off = 4; off > 0; off >>= 1)
                mx = fmaxf(mx, __shfl_xor_sync(0xffffffffu, mx, off));
            const float ex = __expf(lg - mx);
            float den = ex;
            #pragma unroll
            for (int off = 4; off > 0; off >>= 1)
                den += __shfl_xor_sync(0xffffffffu, den, off);
            // lanes 0-7 store logits, lanes 8-15 store probs (same o = lane & 7)
            if (lane < 16) {
                if (lane < 8) out[b * NOUT + o] = lg;
                else          out[half_off + b * NOUT + o] = __fdividef(ex, den);
            }
        }
        return;
    }

    // ======================= GENERAL PATH (w != 0) ============================
    const int sx = sx_s, sy = sy_s;
    const float* inb = input_view + (size_t)b * L_I * IMS * IMS;
    float* v_g = g_v + (size_t)b * 2 * VSZ;

    for (int p = tid; p < 2 * VSZ; p += NTHREADS) v_g[p] = 0.f;

    // r field -> gmem scratch
    float* rb = g_r + (size_t)b * IMS * IMS;
    for (int p = tid; p < IMS * IMS; p += NTHREADS) {
        const int y = p >> 6, x = p & 63;
        float s = comb[18];
        #pragma unroll
        for (int i = 0; i < L_I; ++i)
            #pragma unroll
            for (int kh = 0; kh < 3; ++kh) {
                const int yy = y + kh - 1;
                if ((unsigned)yy >= IMS) continue;
                #pragma unroll
                for (int kw = 0; kw < 3; ++kw) {
                    const int xx = x + kw - 1;
                    if ((unsigned)xx >= IMS) continue;
                    s += comb[i * 9 + kh * 3 + kw] * inb[(i * IMS + yy) * IMS + xx];
                }
            }
        rb[p] = s;
    }
    __syncthreads();

    // qr field -> gmem scratch; v0 = max_q qr
    float* qrb = g_qr + (size_t)b * L_Q * IMS * IMS;
    int cur = 0;
    for (int p = tid; p < IMS * IMS; p += NTHREADS) {
        const int y = p >> 6, x = p & 63;
        float m = -FLT_MAX;
        #pragma unroll
        for (int q = 0; q < L_Q; ++q) {
            float s = 0.f;
            #pragma unroll
            for (int kh = 0; kh < 3; ++kh) {
                const int yy = y + kh - 1;
                if ((unsigned)yy >= IMS) continue;
                #pragma unroll
                for (int kw = 0; kw < 3; ++kw) {
                    const int xx = x + kw - 1;
                    if ((unsigned)xx >= IMS) continue;
                    s += qw_s[q * 9 + kh * 3 + kw] * rb[yy * IMS + xx];
                }
            }
            qrb[q * (IMS * IMS) + p] = s;
            m = fmaxf(m, s);
        }
        v_g[cur * VSZ + (y + 1) * VSTR + (x + 1)] = m;
    }
    __syncthreads();

    const int K = kptr ? kptr[0] : 40;
    for (int it = 0; it < K; ++it) {
        const int nxt = cur ^ 1;
        for (int p = tid; p < IMS * IMS; p += NTHREADS) {
            const int y = p >> 6, x = p & 63;
            const float* vb = v_g + cur * VSZ + y * VSTR + x;
            const float v00 = vb[0],        v01 = vb[1],            v02 = vb[2];
            const float v10 = vb[VSTR],     v11 = vb[VSTR + 1],     v12 = vb[VSTR + 2];
            const float v20 = vb[2 * VSTR], v21 = vb[2 * VSTR + 1], v22 = vb[2 * VSTR + 2];
            float m = -FLT_MAX;
            #pragma unroll
            for (int q = 0; q < L_Q; ++q) {
                const float* wq = w_s + q * 9;
                float s = qrb[q * (IMS * IMS) + p]
                        + wq[0] * v00 + wq[1] * v01 + wq[2] * v02
                        + wq[3] * v10 + wq[4] * v11 + wq[5] * v12
                        + wq[6] * v20 + wq[7] * v21 + wq[8] * v22;
                m = fmaxf(m, s);
            }
            v_g[nxt * VSZ + (y + 1) * VSTR + (x + 1)] = m;
        }
        cur = nxt;
        __syncthreads();
    }

    if (tid < L_Q) {
        const float* vb = v_g + cur * VSZ + sx * VSTR + sy;
        const float* wq = w_s + tid * 9;
        qv[tid] = qrb[tid * (IMS * IMS) + sx * IMS + sy]
                + wq[0] * vb[0]        + wq[1] * vb[1]            + wq[2] * vb[2]
                + wq[3] * vb[VSTR]     + wq[4] * vb[VSTR + 1]     + wq[5] * vb[VSTR + 2]
                + wq[6] * vb[2 * VSTR] + wq[7] * vb[2 * VSTR + 1] + wq[8] * vb[2 * VSTR + 2];
    }
    __syncthreads();
    if (tid == 0) {
        float lg[NOUT], mx = -FLT_MAX;
        #pragma unroll
        for (int o = 0; o < NOUT; ++o) {
            float s = 0.f;
            #pragma unroll
            for (int q = 0; q < L_Q; ++q) s += fc_s[o * L_Q + q] * qv[q];
            lg[o] = s;
            mx = fmaxf(mx, s);
        }
        float den = 0.f, ex[NOUT];
        #pragma unroll
        for (int o = 0; o < NOUT; ++o) { ex[o] = __expf(lg[o] - mx); den += ex[o]; }
        const float inv = 1.f / den;
        #pragma unroll
        for (int o = 0; o < NOUT; ++o) {
            out[b * NOUT + o] = lg[o];
            out[half_off + b * NOUT + o] = ex[o] * inv;
        }
    }
}

extern "C" void kernel_launch(void* const* d_in, const int* in_sizes, int n_in,
                              void* d_out, int out_size) {
    const float* input_view = (const float*)d_in[0];
    const int*   state_x    = (const int*)d_in[1];
    const int*   state_y    = (const int*)d_in[2];

    int base = 3;
    const int* kptr = nullptr;
    if (n_in >= 10) { kptr = (const int*)d_in[3]; base = 4; }

    const float* h_w  = (const float*)d_in[base + 0];
    const float* h_b  = (const float*)d_in[base + 1];
    const float* r_w  = (const float*)d_in[base + 2];
    const float* q_w  = (const float*)d_in[base + 3];
    const float* w    = (const float*)d_in[base + 4];
    const float* fc_w = (const float*)d_in[base + 5];

    const int half_off = out_size / 2;   // logits first half, softmax second half

    vin_kernel<<<BATCH, NTHREADS>>>(input_view, state_x, state_y, kptr,
                                    h_w, h_b, r_w, q_w, w, fc_w,
                                    (float*)d_out, half_off);
}